// round 10
// baseline (speedup 1.0000x reference)
#include <cuda_runtime.h>
#include <cuda_fp16.h>
#include <cstdint>

#define EMBED 384
#define IMG_HW 224
#define GRID_HW 14
#define NPATCH 196
#define M_TOTAL 12544
#define K_TOTAL 768
#define CHAN_STRIDE 50176
#define M_CTA 32
#define G_CTAS 392               // M_TOTAL / 32
#define E_CTAS 1568              // M_TOTAL / 8
#define NCHUNK 24
#define NCONV 24                 // producer blocks (one per K chunk)

// B: fp16, chunk-major, ldmatrix-swizzled: halfs c*12288 + n*32 + (seg^((n>>1)&3))*8 + k7
__device__ __half g_wh[NCHUNK * EMBED * 32];
__device__ int g_flag[NCHUNK];   // zero-init at module load; sticky across replays

#define B_CH_BYTES 24576         // 384*64
#define A_BUF_BYTES 2048         // 32*64
// ---- dynamic smem layout (bytes) ----
#define SM_B0    0               // 3 B stages
#define SM_A0    73728           // 2 A bufs
#define SM_BIAS  77824
#define SM_GAMMA 79360
#define SM_BETA  80896
#define SM_RSUM  82432           // 32 f
#define SM_RSQ   82560
#define SM_MU    82688
#define SM_RS    82816
#define SM_MBAR  82944           // 3 x 8B
#define SMEM_TOTAL 83072

__device__ __forceinline__ uint32_t smem_u32(const void* p) {
    uint32_t a;
    asm("{ .reg .u64 t; cvta.to.shared.u64 t, %1; cvt.u32.u64 %0, t; }"
        : "=r"(a) : "l"(p));
    return a;
}
__device__ __forceinline__ uint32_t pack2(float a, float b) {
    __half2 h = __floats2half2_rn(a, b);
    return *reinterpret_cast<uint32_t*>(&h);
}
__device__ __forceinline__ void wait_flag(int c) {
    volatile int* f = &g_flag[c];
    if (!*f) {
        while (*f == 0) { __nanosleep(64); }
    }
    __threadfence();
}

#define MBAR_INIT(addr, cnt) \
    asm volatile("mbarrier.init.shared.b64 [%0], %1;" :: "r"(addr), "r"(cnt) : "memory")
#define MBAR_EXPECT_TX(addr, bytes) \
    asm volatile("mbarrier.arrive.expect_tx.shared.b64 _, [%0], %1;" \
                 :: "r"(addr), "r"(bytes) : "memory")
#define BULK_CP(dst, src, bytes, mbar) \
    asm volatile("cp.async.bulk.shared::cta.global.mbarrier::complete_tx::bytes " \
                 "[%0], [%1], %2, [%3];" \
                 :: "r"(dst), "l"(src), "r"(bytes), "r"(mbar) : "memory")
#define MBAR_WAIT(addr, par) do {                                              \
    uint32_t _m = (addr); uint32_t _p = (par); uint32_t _d;                    \
    asm volatile("{\n\t.reg .pred p;\n\t"                                      \
        "mbarrier.try_wait.parity.acquire.cta.shared::cta.b64 p, [%1], %2;\n\t"\
        "selp.b32 %0, 1, 0, p;\n\t}"                                           \
        : "=r"(_d) : "r"(_m), "r"(_p) : "memory");                             \
    if (!_d) {                                                                 \
        asm volatile("{\n\t.reg .pred P1;\n\t"                                 \
            "W%=:\n\t"                                                         \
            "mbarrier.try_wait.parity.acquire.cta.shared::cta.b64 P1, [%0], %1, 0x989680;\n\t" \
            "@P1 bra.uni D%=;\n\t"                                             \
            "bra.uni W%=;\n\t"                                                 \
            "D%=:\n\t}" :: "r"(_m), "r"(_p) : "memory");                       \
    }                                                                          \
} while (0)

#define LDSM4(r0, r1, r2, r3, a) \
    asm volatile("ldmatrix.sync.aligned.m8n8.x4.shared.b16 {%0,%1,%2,%3}, [%4];" \
                 : "=r"(r0), "=r"(r1), "=r"(r2), "=r"(r3) : "r"(a))

#define MMA16816(d, a0, a1, a2, a3, b0, b1) \
    asm volatile("mma.sync.aligned.m16n8k16.row.col.f32.f16.f16.f32 " \
                 "{%0,%1,%2,%3}, {%4,%5,%6,%7}, {%8,%9}, {%0,%1,%2,%3};" \
                 : "+f"((d)[0]), "+f"((d)[1]), "+f"((d)[2]), "+f"((d)[3]) \
                 : "r"(a0), "r"(a1), "r"(a2), "r"(a3), "r"(b0), "r"(b1))

// ---------------------------------------------------------------------------
// One fused launch:
//   bid [0,24)        -> W-chunk converter (producer), sets g_flag[bid]
//   bid [24,172)      -> gemm bm = bid-24          (148)
//   bid [172,320)     -> entropy e = bid-172       (148)
//   bid [320,564)     -> gemm bm = bid-320+148     (244)
//   bid [564,1984)    -> entropy e = bid-564+148   (1420)
// ---------------------------------------------------------------------------
__global__ __launch_bounds__(256, 2) void fused_kernel(
    const float* __restrict__ img, const float* __restrict__ w,
    const float* __restrict__ bias, const float* __restrict__ gamma,
    const float* __restrict__ beta, float* __restrict__ out,
    float* __restrict__ ent) {
    extern __shared__ char smem[];
    const int bid = blockIdx.x;
    const int tid = threadIdx.x;
    const int wid = tid >> 5;
    const int lid = tid & 31;

    if (bid < NCONV) {
        // --------------------- W chunk converter ---------------------
        const int cb = bid;
        #pragma unroll
        for (int t = 0; t < 12; t++) {
            int id = tid + 256 * t;          // 0..3071 float4s
            int n = id >> 3;
            int j = id & 7;
            float4 v = *(const float4*)(w + (size_t)n * K_TOTAL + cb * 32 + 4 * j);
            int kin = 4 * j;
            int phys = (kin >> 3) ^ ((n >> 1) & 3);
            uint32_t* dst =
                (uint32_t*)(g_wh + cb * 12288 + n * 32 + phys * 8 + (kin & 7));
            dst[0] = pack2(v.x, v.y);
            dst[1] = pack2(v.z, v.w);
        }
        __threadfence();
        __syncthreads();
        if (tid == 0) *(volatile int*)&g_flag[cb] = 1;
        return;
    }

    const bool is_gemm = (bid < 172) || (bid >= 320 && bid < 564);

    if (!is_gemm) {
        // ------------------------- entropy -------------------------
        const int e = (bid < 320) ? (bid - 172) : (bid - 564 + 148);
        uint32_t (*qbuf)[64] = (uint32_t(*)[64])smem;
        const int m = e * 8 + wid;
        const int b = m / NPATCH;
        const int pidx = m % NPATCH;
        const int gh = pidx / GRID_HW;
        const int gw = pidx % GRID_HW;
        const int prow = lid >> 1;
        const int pcol = (lid & 1) * 8;

        const size_t base = (size_t)(b * 3) * CHAN_STRIDE
                          + (size_t)(gh * 16 + prow) * IMG_HW + (gw * 16 + pcol);
        float4 a0 = *(const float4*)(img + base);
        float4 a1 = *(const float4*)(img + base + 4);
        float4 b0 = *(const float4*)(img + base + CHAN_STRIDE);
        float4 b1 = *(const float4*)(img + base + CHAN_STRIDE + 4);
        float4 c0 = *(const float4*)(img + base + 2 * CHAN_STRIDE);
        float4 c1 = *(const float4*)(img + base + 2 * CHAN_STRIDE + 4);

        float g[8];
        g[0] = (a0.x + b0.x + c0.x) / 3.0f;
        g[1] = (a0.y + b0.y + c0.y) / 3.0f;
        g[2] = (a0.z + b0.z + c0.z) / 3.0f;
        g[3] = (a0.w + b0.w + c0.w) / 3.0f;
        g[4] = (a1.x + b1.x + c1.x) / 3.0f;
        g[5] = (a1.y + b1.y + c1.y) / 3.0f;
        g[6] = (a1.z + b1.z + c1.z) / 3.0f;
        g[7] = (a1.w + b1.w + c1.w) / 3.0f;

        uint32_t q[8];
        #pragma unroll
        for (int i = 0; i < 8; i++)
            q[i] = (uint32_t)(int)fminf(fmaxf(g[i] * 31.0f, 0.0f), 31.0f);
        qbuf[wid][lid * 2]     = q[0] | (q[1] << 8) | (q[2] << 16) | (q[3] << 24);
        qbuf[wid][lid * 2 + 1] = q[4] | (q[5] << 8) | (q[6] << 16) | (q[7] << 24);
        __syncwarp();

        const uint32_t pat = 0x01010101u * (uint32_t)lid;
        int bits = 0;
        #pragma unroll
        for (int i = 0; i < 64; i++) bits += __popc(__vcmpeq4(qbuf[wid][i], pat));

        float p = (float)(bits >> 3) * (1.0f / 256.0f);
        float t = p * log2f(p + 1e-10f);
        #pragma unroll
        for (int o = 16; o; o >>= 1) t += __shfl_xor_sync(0xffffffffu, t, o);
        if (lid == 0) ent[m] = -t * 0.2f;
        return;
    }

    // ---------------------------- gemm + LN ----------------------------
    const int bm = (bid < 172) ? (bid - 24) : (bid - 320 + 148);
    const uint32_t sbase = smem_u32(smem);
    const int qr = lid >> 2;
    const int qc = lid & 3;

    if (tid < 32) {
        ((float*)(smem + SM_RSUM))[tid] = 0.0f;
        ((float*)(smem + SM_RSQ))[tid]  = 0.0f;
    }
    if (tid >= 32 && tid < 32 + 96) {
        int i4 = tid - 32;   // 96 float4s = 384 floats
        ((float4*)(smem + SM_BIAS))[i4]  = ((const float4*)bias)[i4];
        ((float4*)(smem + SM_GAMMA))[i4] = ((const float4*)gamma)[i4];
        ((float4*)(smem + SM_BETA))[i4]  = ((const float4*)beta)[i4];
    }
    if (tid == 0) {
        #pragma unroll
        for (int s = 0; s < 3; s++) {
            wait_flag(s);
            MBAR_INIT(sbase + SM_MBAR + 8 * s, 1);
            MBAR_EXPECT_TX(sbase + SM_MBAR + 8 * s, B_CH_BYTES);
            BULK_CP(sbase + s * B_CH_BYTES,
                    (const char*)g_wh + (size_t)s * B_CH_BYTES, B_CH_BYTES,
                    sbase + SM_MBAR + 8 * s);
        }
    }

    // A gather geometry: 1 float4 per thread per chunk.
    const int arow = tid >> 3;       // 0..31
    const int aj = tid & 7;          // float4 slot
    const float* abase;
    {
        int m = bm * M_CTA + arow;
        abase = img + (size_t)((m / NPATCH) * 3) * CHAN_STRIDE
              + (size_t)(((m % NPATCH) / GRID_HW) * 16) * IMG_HW
              + ((m % NPATCH) % GRID_HW) * 16;
    }
    const uint32_t adst = arow * 64 + (((aj >> 1) ^ ((arow >> 1) & 3)) << 4)
                        + (aj & 1) * 8;
    auto aoff = [&](int c) -> size_t {
        int k = c * 32 + 4 * aj;
        return (size_t)(k >> 8) * CHAN_STRIDE + ((k >> 4) & 15) * IMG_HW + (k & 15);
    };

    // Prologue: A(0) -> buf0; A(1) -> regs.
    float4 areg;
    {
        float4 v = *(const float4*)(abase + aoff(0));
        *(uint2*)(smem + SM_A0 + adst) = make_uint2(pack2(v.x, v.y), pack2(v.z, v.w));
        areg = *(const float4*)(abase + aoff(1));
    }
    __syncthreads();

    float acc[48];
    #pragma unroll
    for (int i = 0; i < 48; i++) acc[i] = 0.0f;

    // lane geometry (ldmatrix)
    const int a_row = ((lid >> 3) & 1) * 8 + (lid & 7);
    const int a_kbit = lid >> 4;
    const int b_noff = ((lid >> 4) & 1) * 8 + (lid & 7);
    const int b_segbit = (lid >> 3) & 1;
    const int xr = (lid & 7) >> 1;

    int s = 0, par = 0, c3 = 0;      // stage, parity, c/3 tracker
    for (int c = 0; c < NCHUNK; c++) {
        MBAR_WAIT(sbase + SM_MBAR + 8 * s, par);

        // Store A(c+1); prefetch A(c+2).
        if (c + 1 < NCHUNK) {
            *(uint2*)(smem + SM_A0 + ((c + 1) & 1) * A_BUF_BYTES + adst) =
                make_uint2(pack2(areg.x, areg.y), pack2(areg.z, areg.w));
            if (c + 2 < NCHUNK) areg = *(const float4*)(abase + aoff(c + 2));
        }

        const uint32_t Bst = sbase + s * B_CH_BYTES;
        const uint32_t Ast = sbase + SM_A0 + (c & 1) * A_BUF_BYTES;
        #pragma unroll
        for (int sh = 0; sh < 2; sh++) {
            uint32_t bf[3][4];
            const int sg = (2 * sh + b_segbit) ^ xr;
            #pragma unroll
            for (int tp = 0; tp < 3; tp++) {
                int n = 48 * wid + 16 * tp + b_noff;
                LDSM4(bf[tp][0], bf[tp][1], bf[tp][2], bf[tp][3],
                      Bst + n * 64 + sg * 16);
            }
            const int aseg = (2 * sh + a_kbit) ^ xr;
            #pragma unroll
            for (int i = 0; i < 2; i++) {
                uint32_t a0, a1, a2, a3;
                LDSM4(a0, a1, a2, a3, Ast + (16 * i + a_row) * 64 + aseg * 16);
                #pragma unroll
                for (int tp = 0; tp < 3; tp++) {
                    MMA16816(acc + (i * 6 + 2 * tp) * 4, a0, a1, a2, a3,
                             bf[tp][0], bf[tp][1]);
                    MMA16816(acc + (i * 6 + 2 * tp + 1) * 4, a0, a1, a2, a3,
                             bf[tp][2], bf[tp][3]);
                }
            }
        }
        __syncthreads();
        if (tid == 0 && c + 3 < NCHUNK) {
            wait_flag(c + 3);
            MBAR_EXPECT_TX(sbase + SM_MBAR + 8 * s, B_CH_BYTES);
            BULK_CP(sbase + s * B_CH_BYTES,
                    (const char*)g_wh + (size_t)(c + 3) * B_CH_BYTES,
                    B_CH_BYTES, sbase + SM_MBAR + 8 * s);
        }
        if (++s == 3) { s = 0; }
        if (++c3 == 3) { c3 = 0; par ^= 1; }
    }

    // ---------------- fused LayerNorm epilogue ----------------
    float* rsum = (float*)(smem + SM_RSUM);
    float* rsq  = (float*)(smem + SM_RSQ);
    const float* sbias = (const float*)(smem + SM_BIAS);

    float2 bs2[6];
    #pragma unroll
    for (int t = 0; t < 6; t++)
        bs2[t] = *(const float2*)&sbias[48 * wid + 8 * t + 2 * qc];

    #pragma unroll
    for (int i = 0; i < 2; i++) {
        float s0 = 0, q0 = 0, s1 = 0, q1 = 0;
        #pragma unroll
        for (int t = 0; t < 6; t++) {
            float* d = acc + (i * 6 + t) * 4;
            d[0] += bs2[t].x; d[1] += bs2[t].y;
            d[2] += bs2[t].x; d[3] += bs2[t].y;
            s0 += d[0] + d[1]; q0 += d[0] * d[0] + d[1] * d[1];
            s1 += d[2] + d[3]; q1 += d[2] * d[2] + d[3] * d[3];
        }
        #pragma unroll
        for (int o = 1; o <= 2; o <<= 1) {
            s0 += __shfl_xor_sync(0xffffffffu, s0, o);
            q0 += __shfl_xor_sync(0xffffffffu, q0, o);
            s1 += __shfl_xor_sync(0xffffffffu, s1, o);
            q1 += __shfl_xor_sync(0xffffffffu, q1, o);
        }
        if (qc == 0) {
            atomicAdd(&rsum[16 * i + qr], s0);
            atomicAdd(&rsq[16 * i + qr], q0);
            atomicAdd(&rsum[16 * i + qr + 8], s1);
            atomicAdd(&rsq[16 * i + qr + 8], q1);
        }
    }
    __syncthreads();

    float* smu = (float*)(smem + SM_MU);
    float* srs = (float*)(smem + SM_RS);
    if (tid < 32) {
        float mu = rsum[tid] * (1.0f / EMBED);
        float vv = rsq[tid] * (1.0f / EMBED) - mu * mu;
        smu[tid] = mu;
        srs[tid] = rsqrtf(fmaxf(vv, 0.0f) + 1e-5f);
    }
    __syncthreads();

    const float* sg = (const float*)(smem + SM_GAMMA);
    const float* sb = (const float*)(smem + SM_BETA);
    float2 g2[6], be2[6];
    #pragma unroll
    for (int t = 0; t < 6; t++) {
        g2[t]  = *(const float2*)&sg[48 * wid + 8 * t + 2 * qc];
        be2[t] = *(const float2*)&sb[48 * wid + 8 * t + 2 * qc];
    }

    #pragma unroll
    for (int i = 0; i < 2; i++) {
        const int r0 = 16 * i + qr;
        const float mu0 = smu[r0], rs0 = srs[r0];
        const float mu1 = smu[r0 + 8], rs1 = srs[r0 + 8];
        float* o0 = out + (size_t)(bm * M_CTA + r0) * EMBED + 48 * wid + 2 * qc;
        float* o1 = o0 + 8 * (size_t)EMBED;
        #pragma unroll
        for (int t = 0; t < 6; t++) {
            float* d = acc + (i * 6 + t) * 4;
            float2 w0, w1;
            w0.x = (d[0] - mu0) * rs0 * g2[t].x + be2[t].x;
            w0.y = (d[1] - mu0) * rs0 * g2[t].y + be2[t].y;
            w1.x = (d[2] - mu1) * rs1 * g2[t].x + be2[t].x;
            w1.y = (d[3] - mu1) * rs1 * g2[t].y + be2[t].y;
            *(float2*)(o0 + 8 * t) = w0;
            *(float2*)(o1 + 8 * t) = w1;
        }
    }
}

// ---------------------------------------------------------------------------
extern "C" void kernel_launch(void* const* d_in, const int* in_sizes, int n_in,
                              void* d_out, int out_size) {
    const float* images = (const float*)d_in[0];
    const float* proj_w = (const float*)d_in[1];
    const float* proj_b = (const float*)d_in[2];
    const float* ln_g   = (const float*)d_in[3];
    const float* ln_b   = (const float*)d_in[4];
    float* out = (float*)d_out;

    float* x   = out;
    float* ent = out + (size_t)M_TOTAL * EMBED;

    cudaFuncSetAttribute(fused_kernel,
                         cudaFuncAttributeMaxDynamicSharedMemorySize, SMEM_TOTAL);

    fused_kernel<<<NCONV + G_CTAS + E_CTAS, 256, SMEM_TOTAL>>>(
        images, proj_w, proj_b, ln_g, ln_b, x, ent);
}

// round 15
// speedup vs baseline: 1.5756x; 1.5756x over previous
#include <cuda_runtime.h>
#include <cuda_fp16.h>
#include <cstdint>

#define EMBED 384
#define IMG_HW 224
#define GRID_HW 14
#define NPATCH 196
#define M_TOTAL 12544
#define K_TOTAL 768
#define CHAN_STRIDE 50176
#define M_CTA 32
#define G_CTAS 392               // M_TOTAL / 32
#define NCHUNK 24

// B: fp16, chunk-major, ldmatrix-swizzled: halfs c*12288 + n*32 + (seg^((n>>1)&3))*8 + k7
__device__ __half g_wh[NCHUNK * EMBED * 32];

#define B_CH_BYTES 24576         // 384*64
#define A_BUF_BYTES 2048         // 32*64
// ---- dynamic smem layout (bytes) ----
#define SM_B0    0               // 3 B stages
#define SM_A0    73728           // 2 A bufs
#define SM_BIAS  77824
#define SM_GAMMA 79360
#define SM_BETA  80896
#define SM_RSUM  82432           // 32 f
#define SM_RSQ   82560
#define SM_MU    82688
#define SM_RS    82816
#define SM_MBAR  82944           // 3 x 8B
#define SM_HIST  83072           // 32 rows x 32 bins x int
#define SMEM_TOTAL 87168

__device__ __forceinline__ uint32_t smem_u32(const void* p) {
    uint32_t a;
    asm("{ .reg .u64 t; cvta.to.shared.u64 t, %1; cvt.u32.u64 %0, t; }"
        : "=r"(a) : "l"(p));
    return a;
}
__device__ __forceinline__ uint32_t pack2(float a, float b) {
    __half2 h = __floats2half2_rn(a, b);
    return *reinterpret_cast<uint32_t*>(&h);
}

#define MBAR_INIT(addr, cnt) \
    asm volatile("mbarrier.init.shared.b64 [%0], %1;" :: "r"(addr), "r"(cnt) : "memory")
#define MBAR_EXPECT_TX(addr, bytes) \
    asm volatile("mbarrier.arrive.expect_tx.shared.b64 _, [%0], %1;" \
                 :: "r"(addr), "r"(bytes) : "memory")
#define BULK_CP(dst, src, bytes, mbar) \
    asm volatile("cp.async.bulk.shared::cta.global.mbarrier::complete_tx::bytes " \
                 "[%0], [%1], %2, [%3];" \
                 :: "r"(dst), "l"(src), "r"(bytes), "r"(mbar) : "memory")
#define MBAR_WAIT(addr, par) do {                                              \
    uint32_t _m = (addr); uint32_t _p = (par); uint32_t _d;                    \
    asm volatile("{\n\t.reg .pred p;\n\t"                                      \
        "mbarrier.try_wait.parity.acquire.cta.shared::cta.b64 p, [%1], %2;\n\t"\
        "selp.b32 %0, 1, 0, p;\n\t}"                                           \
        : "=r"(_d) : "r"(_m), "r"(_p) : "memory");                             \
    if (!_d) {                                                                 \
        asm volatile("{\n\t.reg .pred P1;\n\t"                                 \
            "W%=:\n\t"                                                         \
            "mbarrier.try_wait.parity.acquire.cta.shared::cta.b64 P1, [%0], %1, 0x989680;\n\t" \
            "@P1 bra.uni D%=;\n\t"                                             \
            "bra.uni W%=;\n\t"                                                 \
            "D%=:\n\t}" :: "r"(_m), "r"(_p) : "memory");                       \
    }                                                                          \
} while (0)

#define LDSM4(r0, r1, r2, r3, a) \
    asm volatile("ldmatrix.sync.aligned.m8n8.x4.shared.b16 {%0,%1,%2,%3}, [%4];" \
                 : "=r"(r0), "=r"(r1), "=r"(r2), "=r"(r3) : "r"(a))

#define MMA16816(d, a0, a1, a2, a3, b0, b1) \
    asm volatile("mma.sync.aligned.m16n8k16.row.col.f32.f16.f16.f32 " \
                 "{%0,%1,%2,%3}, {%4,%5,%6,%7}, {%8,%9}, {%0,%1,%2,%3};" \
                 : "+f"((d)[0]), "+f"((d)[1]), "+f"((d)[2]), "+f"((d)[3]) \
                 : "r"(a0), "r"(a1), "r"(a2), "r"(a3), "r"(b0), "r"(b1))

// ---------------------------------------------------------------------------
// W fp16 convert: 73728 float4s, 72 blocks x 256 thr x 4.
// ---------------------------------------------------------------------------
__global__ __launch_bounds__(256) void wcvt_kernel(const float* __restrict__ w) {
    #pragma unroll
    for (int r = 0; r < 4; r++) {
        int i = blockIdx.x * 256 + threadIdx.x + r * 18432;
        int n = i / 192;
        int k = (i % 192) * 4;
        float4 v = *(const float4*)(w + (size_t)n * K_TOTAL + k);
        int c = k >> 5;
        int kin = k & 31;
        int phys = (kin >> 3) ^ ((n >> 1) & 3);
        uint32_t* dst = (uint32_t*)(g_wh + c * 12288 + n * 32 + phys * 8 + (kin & 7));
        dst[0] = pack2(v.x, v.y);
        dst[1] = pack2(v.z, v.w);
    }
}

// ---------------------------------------------------------------------------
// Fused GEMM + bias + LayerNorm + patch entropy. One block per 32 M-rows.
// K chunks processed channel-interleaved: i -> c = (i%3)*8 + i/3, so each
// pixel's 3 channel values hit the same thread in 3 consecutive chunks;
// a float4 carry accumulates gray sums, histogrammed into smem.
// ---------------------------------------------------------------------------
__global__ __launch_bounds__(256, 2) void fused_kernel(
    const float* __restrict__ img, const float* __restrict__ bias,
    const float* __restrict__ gamma, const float* __restrict__ beta,
    float* __restrict__ out, float* __restrict__ ent) {
    extern __shared__ char smem[];
    const int bid = blockIdx.x;
    const int tid = threadIdx.x;
    const int wid = tid >> 5;
    const int lid = tid & 31;
    const int bm = bid;
    const uint32_t sbase = smem_u32(smem);
    const int qr = lid >> 2;
    const int qc = lid & 3;

    int* hist = (int*)(smem + SM_HIST);
    #pragma unroll
    for (int z = 0; z < 4; z++) hist[tid + 256 * z] = 0;

    if (tid < 32) {
        ((float*)(smem + SM_RSUM))[tid] = 0.0f;
        ((float*)(smem + SM_RSQ))[tid]  = 0.0f;
    }
    if (tid >= 32 && tid < 32 + 96) {
        int i4 = tid - 32;   // 96 float4s = 384 floats
        ((float4*)(smem + SM_BIAS))[i4]  = ((const float4*)bias)[i4];
        ((float4*)(smem + SM_GAMMA))[i4] = ((const float4*)gamma)[i4];
        ((float4*)(smem + SM_BETA))[i4]  = ((const float4*)beta)[i4];
    }
    if (tid == 0) {
        // Stage s starts with chunk c_seq[s] = s*8 (channel s, group 0).
        #pragma unroll
        for (int s = 0; s < 3; s++) {
            MBAR_INIT(sbase + SM_MBAR + 8 * s, 1);
            MBAR_EXPECT_TX(sbase + SM_MBAR + 8 * s, B_CH_BYTES);
            BULK_CP(sbase + s * B_CH_BYTES,
                    (const char*)g_wh + (size_t)(s * 8) * B_CH_BYTES, B_CH_BYTES,
                    sbase + SM_MBAR + 8 * s);
        }
    }

    // A gather geometry: 1 float4 per thread per chunk.
    const int arow = tid >> 3;       // 0..31 : patch row within CTA
    const int aj = tid & 7;          // float4 slot
    const float* abase;
    {
        int m = bm * M_CTA + arow;
        abase = img + (size_t)((m / NPATCH) * 3) * CHAN_STRIDE
              + (size_t)(((m % NPATCH) / GRID_HW) * 16) * IMG_HW
              + ((m % NPATCH) % GRID_HW) * 16;
    }
    const uint32_t adst = arow * 64 + (((aj >> 1) ^ ((arow >> 1) & 3)) << 4)
                        + (aj & 1) * 8;
    // chunk c = ph*8 + grp  ->  k = ph*256 + grp*32 + 4*aj
    auto aoff = [&](int ph, int grp) -> size_t {
        int pix = grp * 32 + 4 * aj;
        return (size_t)ph * CHAN_STRIDE + (pix >> 4) * IMG_HW + (pix & 15);
    };

    // Prologue: A(i=0: ph0,g0) -> buf0 + entropy carry; A(i=1: ph1,g0) -> regs.
    float4 carry, areg;
    {
        float4 v = *(const float4*)(abase + aoff(0, 0));
        *(uint2*)(smem + SM_A0 + adst) = make_uint2(pack2(v.x, v.y), pack2(v.z, v.w));
        carry = v;                              // j=0: ph 0
        areg = *(const float4*)(abase + aoff(1, 0));
    }
    __syncthreads();

    float acc[48];
    #pragma unroll
    for (int i = 0; i < 48; i++) acc[i] = 0.0f;

    // lane geometry (ldmatrix)
    const int a_row = ((lid >> 3) & 1) * 8 + (lid & 7);
    const int a_kbit = lid >> 4;
    const int b_noff = ((lid >> 4) & 1) * 8 + (lid & 7);
    const int b_segbit = (lid >> 3) & 1;
    const int xr = (lid & 7) >> 1;

    // j = i+2 counters for A prefetch (ph2, grp2), current-c counters for B.
    int ph2 = 2, grp2 = 0;          // c_seq[2]
    int phc = 0, grpc = 0;          // c_seq[0]
    int s = 0, par = 0, c3 = 0;

    for (int i = 0; i < NCHUNK; i++) {
        MBAR_WAIT(sbase + SM_MBAR + 8 * s, par);

        // Store A(i+1) + entropy step (j = i+1); prefetch A(i+2).
        if (i + 1 < NCHUNK) {
            *(uint2*)(smem + SM_A0 + ((i + 1) & 1) * A_BUF_BYTES + adst) =
                make_uint2(pack2(areg.x, areg.y), pack2(areg.z, areg.w));
            const int jph = (i + 1) % 3;
            if (jph == 0) {
                carry = areg;
            } else if (jph == 1) {
                carry.x += areg.x; carry.y += areg.y;
                carry.z += areg.z; carry.w += areg.w;
            } else {
                float g0 = (carry.x + areg.x) * (1.0f / 3.0f);
                float g1 = (carry.y + areg.y) * (1.0f / 3.0f);
                float g2 = (carry.z + areg.z) * (1.0f / 3.0f);
                float g3 = (carry.w + areg.w) * (1.0f / 3.0f);
                int* hrow = hist + arow * 32;
                atomicAdd(hrow + (int)fminf(fmaxf(g0 * 31.0f, 0.0f), 31.0f), 1);
                atomicAdd(hrow + (int)fminf(fmaxf(g1 * 31.0f, 0.0f), 31.0f), 1);
                atomicAdd(hrow + (int)fminf(fmaxf(g2 * 31.0f, 0.0f), 31.0f), 1);
                atomicAdd(hrow + (int)fminf(fmaxf(g3 * 31.0f, 0.0f), 31.0f), 1);
            }
            if (i + 2 < NCHUNK) {
                areg = *(const float4*)(abase + aoff(ph2, grp2));
                if (++ph2 == 3) { ph2 = 0; grp2++; }
            }
        }

        const uint32_t Bst = sbase + s * B_CH_BYTES;
        const uint32_t Ast = sbase + SM_A0 + (i & 1) * A_BUF_BYTES;
        #pragma unroll
        for (int sh = 0; sh < 2; sh++) {
            uint32_t bf[3][4];
            const int sg = (2 * sh + b_segbit) ^ xr;
            #pragma unroll
            for (int tp = 0; tp < 3; tp++) {
                int n = 48 * wid + 16 * tp + b_noff;
                LDSM4(bf[tp][0], bf[tp][1], bf[tp][2], bf[tp][3],
                      Bst + n * 64 + sg * 16);
            }
            const int aseg = (2 * sh + a_kbit) ^ xr;
            #pragma unroll
            for (int ii = 0; ii < 2; ii++) {
                uint32_t a0, a1, a2, a3;
                LDSM4(a0, a1, a2, a3, Ast + (16 * ii + a_row) * 64 + aseg * 16);
                #pragma unroll
                for (int tp = 0; tp < 3; tp++) {
                    MMA16816(acc + (ii * 6 + 2 * tp) * 4, a0, a1, a2, a3,
                             bf[tp][0], bf[tp][1]);
                    MMA16816(acc + (ii * 6 + 2 * tp + 1) * 4, a0, a1, a2, a3,
                             bf[tp][2], bf[tp][3]);
                }
            }
        }
        __syncthreads();
        // Refill stage s with the next chunk of the SAME channel: c_cur + 1.
        if (tid == 0 && i + 3 < NCHUNK) {
            const int cnext = phc * 8 + grpc + 1;
            MBAR_EXPECT_TX(sbase + SM_MBAR + 8 * s, B_CH_BYTES);
            BULK_CP(sbase + s * B_CH_BYTES,
                    (const char*)g_wh + (size_t)cnext * B_CH_BYTES,
                    B_CH_BYTES, sbase + SM_MBAR + 8 * s);
        }
        if (++phc == 3) { phc = 0; grpc++; }
        if (++s == 3) { s = 0; }
        if (++c3 == 3) { c3 = 0; par ^= 1; }
    }

    // ---------------- fused LayerNorm epilogue ----------------
    float* rsum = (float*)(smem + SM_RSUM);
    float* rsq  = (float*)(smem + SM_RSQ);
    const float* sbias = (const float*)(smem + SM_BIAS);

    float2 bs2[6];
    #pragma unroll
    for (int t = 0; t < 6; t++)
        bs2[t] = *(const float2*)&sbias[48 * wid + 8 * t + 2 * qc];

    #pragma unroll
    for (int i = 0; i < 2; i++) {
        float s0 = 0, q0 = 0, s1 = 0, q1 = 0;
        #pragma unroll
        for (int t = 0; t < 6; t++) {
            float* d = acc + (i * 6 + t) * 4;
            d[0] += bs2[t].x; d[1] += bs2[t].y;
            d[2] += bs2[t].x; d[3] += bs2[t].y;
            s0 += d[0] + d[1]; q0 += d[0] * d[0] + d[1] * d[1];
            s1 += d[2] + d[3]; q1 += d[2] * d[2] + d[3] * d[3];
        }
        #pragma unroll
        for (int o = 1; o <= 2; o <<= 1) {
            s0 += __shfl_xor_sync(0xffffffffu, s0, o);
            q0 += __shfl_xor_sync(0xffffffffu, q0, o);
            s1 += __shfl_xor_sync(0xffffffffu, s1, o);
            q1 += __shfl_xor_sync(0xffffffffu, q1, o);
        }
        if (qc == 0) {
            atomicAdd(&rsum[16 * i + qr], s0);
            atomicAdd(&rsq[16 * i + qr], q0);
            atomicAdd(&rsum[16 * i + qr + 8], s1);
            atomicAdd(&rsq[16 * i + qr + 8], q1);
        }
    }
    __syncthreads();

    // Entropy reduction: 8 warps x 4 rows; lane = bin.
    {
        #pragma unroll
        for (int rr = 0; rr < 4; rr++) {
            const int r = wid * 4 + rr;
            float p = (float)hist[r * 32 + lid] * (1.0f / 256.0f);
            float t = p * log2f(p + 1e-10f);
            #pragma unroll
            for (int o = 16; o; o >>= 1) t += __shfl_xor_sync(0xffffffffu, t, o);
            if (lid == 0) ent[bm * M_CTA + r] = -t * 0.2f;
        }
    }

    float* smu = (float*)(smem + SM_MU);
    float* srs = (float*)(smem + SM_RS);
    if (tid < 32) {
        float mu = rsum[tid] * (1.0f / EMBED);
        float vv = rsq[tid] * (1.0f / EMBED) - mu * mu;
        smu[tid] = mu;
        srs[tid] = rsqrtf(fmaxf(vv, 0.0f) + 1e-5f);
    }
    __syncthreads();

    const float* sg = (const float*)(smem + SM_GAMMA);
    const float* sb = (const float*)(smem + SM_BETA);
    float2 g2[6], be2[6];
    #pragma unroll
    for (int t = 0; t < 6; t++) {
        g2[t]  = *(const float2*)&sg[48 * wid + 8 * t + 2 * qc];
        be2[t] = *(const float2*)&sb[48 * wid + 8 * t + 2 * qc];
    }

    #pragma unroll
    for (int i = 0; i < 2; i++) {
        const int r0 = 16 * i + qr;
        const float mu0 = smu[r0], rs0 = srs[r0];
        const float mu1 = smu[r0 + 8], rs1 = srs[r0 + 8];
        float* o0 = out + (size_t)(bm * M_CTA + r0) * EMBED + 48 * wid + 2 * qc;
        float* o1 = o0 + 8 * (size_t)EMBED;
        #pragma unroll
        for (int t = 0; t < 6; t++) {
            float* d = acc + (i * 6 + t) * 4;
            float2 w0, w1;
            w0.x = (d[0] - mu0) * rs0 * g2[t].x + be2[t].x;
            w0.y = (d[1] - mu0) * rs0 * g2[t].y + be2[t].y;
            w1.x = (d[2] - mu1) * rs1 * g2[t].x + be2[t].x;
            w1.y = (d[3] - mu1) * rs1 * g2[t].y + be2[t].y;
            *(float2*)(o0 + 8 * t) = w0;
            *(float2*)(o1 + 8 * t) = w1;
        }
    }
}

// ---------------------------------------------------------------------------
extern "C" void kernel_launch(void* const* d_in, const int* in_sizes, int n_in,
                              void* d_out, int out_size) {
    const float* images = (const float*)d_in[0];
    const float* proj_w = (const float*)d_in[1];
    const float* proj_b = (const float*)d_in[2];
    const float* ln_g   = (const float*)d_in[3];
    const float* ln_b   = (const float*)d_in[4];
    float* out = (float*)d_out;

    float* x   = out;
    float* ent = out + (size_t)M_TOTAL * EMBED;

    cudaFuncSetAttribute(fused_kernel,
                         cudaFuncAttributeMaxDynamicSharedMemorySize, SMEM_TOTAL);

    wcvt_kernel<<<72, 256>>>(proj_w);
    fused_kernel<<<G_CTAS, 256, SMEM_TOTAL>>>(images, proj_b, ln_g, ln_b, x, ent);
}